// round 9
// baseline (speedup 1.0000x reference)
#include <cuda_runtime.h>
#include <cuda_fp16.h>

#define NUM_USERS 100000
#define NUM_ITEMS 100000
#define N_NODES   200000
#define EMB       64
#define N_EDGES   3200000
#define SCAN_CHUNK 1024
#define NB ((N_NODES + SCAN_CHUNK - 1) / SCAN_CHUNK)   // 196

// ---------------- scratch (no allocations allowed) ----------------
// g_cnt is zero at module load and k_scan23 re-zeroes it after use, so every
// call (correctness, capture, every replay) sees zeroed counters.
__device__ int  g_cnt[N_NODES];
__device__ int  g_off[N_NODES];
__device__ int  g_cur[N_NODES];
__device__ int  g_bsum[NB];
__device__ __align__(16) int2   g_edge[N_EDGES];               // {col, w-bits} sorted by row
__device__ __align__(16) __half g_h0[(size_t)N_NODES * EMB];   // ego0
__device__ __align__(16) __half g_h1[(size_t)N_NODES * EMB];   // ego1
__device__ __align__(16) __half g_h2[(size_t)N_NODES * EMB];   // ego2

// -------- init + histogram fused (g_cnt guaranteed zero on entry) ---------
__global__ void k_init_hist(const float* __restrict__ user,
                            const float* __restrict__ item,
                            const int* __restrict__ edge_row) {
    int i = blockIdx.x * blockDim.x + threadIdx.x;
    int stride = gridDim.x * blockDim.x;
    const int NV4 = (N_NODES * EMB) / 4;
    const int UV4 = (NUM_USERS * EMB) / 4;
    const float4* u4 = reinterpret_cast<const float4*>(user);
    const float4* t4 = reinterpret_cast<const float4*>(item);
    uint2* h4 = reinterpret_cast<uint2*>(g_h0);
    for (int j = i; j < NV4; j += stride) {
        float4 f = (j < UV4) ? u4[j] : t4[j - UV4];
        __half2 a = __floats2half2_rn(f.x, f.y);
        __half2 b = __floats2half2_rn(f.z, f.w);
        uint2 p;
        p.x = *reinterpret_cast<unsigned*>(&a);
        p.y = *reinterpret_cast<unsigned*>(&b);
        h4[j] = p;
    }
    for (int e = i; e < N_EDGES; e += stride)
        atomicAdd(&g_cnt[__ldg(&edge_row[e])], 1);
}

// ---------------- scan stage 1: per-chunk inclusive scan ------------------
__global__ void k_scan1() {
    __shared__ int s[SCAN_CHUNK];
    int tid = threadIdx.x;
    int gid = blockIdx.x * SCAN_CHUNK + tid;
    int v = (gid < N_NODES) ? g_cnt[gid] : 0;
    s[tid] = v;
    __syncthreads();
    for (int d = 1; d < SCAN_CHUNK; d <<= 1) {
        int t = (tid >= d) ? s[tid - d] : 0;
        __syncthreads();
        s[tid] += t;
        __syncthreads();
    }
    if (gid < N_NODES) g_off[gid] = s[tid];
    if (tid == SCAN_CHUNK - 1) g_bsum[blockIdx.x] = s[tid];
}

// ---------------- scan stage 2+3 fused + g_cnt reset ----------------------
__global__ void k_scan23() {
    __shared__ int s[256];
    int tid = threadIdx.x;
    s[tid] = (tid < NB) ? g_bsum[tid] : 0;
    __syncthreads();
    for (int d = 1; d < 256; d <<= 1) {
        int t = (tid >= d) ? s[tid - d] : 0;
        __syncthreads();
        s[tid] += t;
        __syncthreads();
    }
    int i = blockIdx.x * blockDim.x + tid;
    if (i < N_NODES) {
        int chunk = i / SCAN_CHUNK;
        int bpre = (chunk == 0) ? 0 : s[chunk - 1];
        int excl = g_off[i] - g_cnt[i] + bpre;
        g_off[i] = excl;
        g_cur[i] = excl;
        g_cnt[i] = 0;              // restore invariant for next replay
    }
}

// ---------------- scatter: 4 edges/thread, independent chains -------------
#define SCAT_PER_THREAD 4
__global__ __launch_bounds__(256) void k_scatter(const int* __restrict__ edge_row,
                          const int* __restrict__ edge_col,
                          const float* __restrict__ edge_w) {
    int t = blockIdx.x * blockDim.x + threadIdx.x;
    int base = t * SCAT_PER_THREAD;
    if (base >= N_EDGES) return;

    if (base + SCAT_PER_THREAD <= N_EDGES) {
        // full vectorized path: int4/float4 coalesced loads
        int4  r4 = __ldg(reinterpret_cast<const int4*>(edge_row + base));
        int4  c4 = __ldg(reinterpret_cast<const int4*>(edge_col + base));
        float4 w4 = __ldg(reinterpret_cast<const float4*>(edge_w + base));
        int r[4] = {r4.x, r4.y, r4.z, r4.w};
        int c[4] = {c4.x, c4.y, c4.z, c4.w};
        float w[4] = {w4.x, w4.y, w4.z, w4.w};
        int pos[4];
#pragma unroll
        for (int j = 0; j < 4; j++)
            pos[j] = atomicAdd(&g_cur[r[j]], 1);   // 4 independent atomics in flight
#pragma unroll
        for (int j = 0; j < 4; j++) {
            int2 pk; pk.x = c[j]; pk.y = __float_as_int(w[j]);
            g_edge[pos[j]] = pk;
        }
    } else {
        for (int e = base; e < N_EDGES; e++) {
            int r = __ldg(&edge_row[e]);
            int pos = atomicAdd(&g_cur[r], 1);
            int2 pk; pk.x = __ldg(&edge_col[e]); pk.y = __float_as_int(__ldg(&edge_w[e]));
            g_edge[pos] = pk;
        }
    }
}

// ---------------- wide-gather CSR SpMM, depth-2 pipelined ----------------
// One warp per row. g = lane>>3 (edge within 4-edge batch), s = lane&7
// (16B chunk of the 128B fp16 row). The gather for batch i+1 is issued
// before batch i is consumed, so gather latency overlaps across iterations.
// MODE 0: x=g_h0 -> y=g_h1
// MODE 1: x=g_h1 -> y=g_h2
// MODE 2: x=g_h2;  out = (h1 + h2 + acc)/3
template <int MODE>
__global__ __launch_bounds__(256) void k_spmm(float* __restrict__ out) {
    int warp = (blockIdx.x * blockDim.x + threadIdx.x) >> 5;
    int lane = threadIdx.x & 31;
    if (warp >= N_NODES) return;
    int g = lane >> 3;
    int s = lane & 7;

    int start = g_off[warp];
    int end   = (warp == N_NODES - 1) ? N_EDGES : g_off[warp + 1];

    const __half* xp = (MODE == 0) ? g_h0 : (MODE == 1) ? g_h1 : g_h2;
    const uint4* __restrict__ x4 = reinterpret_cast<const uint4*>(xp);

    float acc[8];
#pragma unroll
    for (int j = 0; j < 8; j++) acc[j] = 0.f;

    if (start < end) {
        // ---- prime depth-2 pipeline ----
        bool v0 = (start + g) < end;
        int2 e0 = __ldg(&g_edge[v0 ? (start + g) : (end - 1)]);
        float w0 = v0 ? __int_as_float(e0.y) : 0.f;
        uint4 hv0 = __ldg(&x4[e0.x * 8 + s]);      // gather for batch 0 in flight

        float w1 = 0.f;
        int   c1 = 0;
        {
            int eb1 = start + 4;
            if (eb1 < end) {
                bool v1 = (eb1 + g) < end;
                int2 e1 = __ldg(&g_edge[v1 ? (eb1 + g) : (end - 1)]);
                w1 = v1 ? __int_as_float(e1.y) : 0.f;
                c1 = e1.x;
            }
        }

        for (int e = start; e < end; e += 4) {
            uint4 cur = hv0;
            float w   = w0;
            int en = e + 4;
            if (en < end) {
                hv0 = __ldg(&x4[(size_t)c1 * 8 + s]);   // gather batch i+1 NOW
                w0 = w1;
                int e2b = en + 4;
                if (e2b < end) {                        // prefetch edges batch i+2
                    bool v2 = (e2b + g) < end;
                    int2 e2 = __ldg(&g_edge[v2 ? (e2b + g) : (end - 1)]);
                    w1 = v2 ? __int_as_float(e2.y) : 0.f;
                    c1 = e2.x;
                }
            }
            __half2 p0 = *reinterpret_cast<__half2*>(&cur.x);
            __half2 p1 = *reinterpret_cast<__half2*>(&cur.y);
            __half2 p2 = *reinterpret_cast<__half2*>(&cur.z);
            __half2 p3 = *reinterpret_cast<__half2*>(&cur.w);
            float2 f0 = __half22float2(p0);
            float2 f1 = __half22float2(p1);
            float2 f2 = __half22float2(p2);
            float2 f3 = __half22float2(p3);
            acc[0] = fmaf(w, f0.x, acc[0]);
            acc[1] = fmaf(w, f0.y, acc[1]);
            acc[2] = fmaf(w, f1.x, acc[2]);
            acc[3] = fmaf(w, f1.y, acc[3]);
            acc[4] = fmaf(w, f2.x, acc[4]);
            acc[5] = fmaf(w, f2.y, acc[5]);
            acc[6] = fmaf(w, f3.x, acc[6]);
            acc[7] = fmaf(w, f3.y, acc[7]);
        }
    }

    // reduce across the 4 edge groups
#pragma unroll
    for (int j = 0; j < 8; j++) {
        acc[j] += __shfl_xor_sync(0xFFFFFFFF, acc[j], 8);
        acc[j] += __shfl_xor_sync(0xFFFFFFFF, acc[j], 16);
    }

    if (g == 0) {
        int ridx = warp * 8 + s;                 // uint4 index of this 16B chunk
        if (MODE != 2) {
            __half2 y0 = __floats2half2_rn(acc[0], acc[1]);
            __half2 y1 = __floats2half2_rn(acc[2], acc[3]);
            __half2 y2 = __floats2half2_rn(acc[4], acc[5]);
            __half2 y3 = __floats2half2_rn(acc[6], acc[7]);
            uint4 pk;
            pk.x = *reinterpret_cast<unsigned*>(&y0);
            pk.y = *reinterpret_cast<unsigned*>(&y1);
            pk.z = *reinterpret_cast<unsigned*>(&y2);
            pk.w = *reinterpret_cast<unsigned*>(&y3);
            uint4* yp = reinterpret_cast<uint4*>((MODE == 0) ? g_h1 : g_h2);
            yp[ridx] = pk;
        } else {
            // out = (ego1 + ego2 + ego3) / 3
            uint4 a1 = __ldg(&reinterpret_cast<const uint4*>(g_h1)[ridx]);
            uint4 a2 = __ldg(&reinterpret_cast<const uint4*>(g_h2)[ridx]);
            const float sc = 1.0f / 3.0f;
            float4 o0, o1;
            float2 t;
            t = __half22float2(*reinterpret_cast<__half2*>(&a1.x));
            o0.x = t.x; o0.y = t.y;
            t = __half22float2(*reinterpret_cast<__half2*>(&a1.y));
            o0.z = t.x; o0.w = t.y;
            t = __half22float2(*reinterpret_cast<__half2*>(&a1.z));
            o1.x = t.x; o1.y = t.y;
            t = __half22float2(*reinterpret_cast<__half2*>(&a1.w));
            o1.z = t.x; o1.w = t.y;
            t = __half22float2(*reinterpret_cast<__half2*>(&a2.x));
            o0.x += t.x; o0.y += t.y;
            t = __half22float2(*reinterpret_cast<__half2*>(&a2.y));
            o0.z += t.x; o0.w += t.y;
            t = __half22float2(*reinterpret_cast<__half2*>(&a2.z));
            o1.x += t.x; o1.y += t.y;
            t = __half22float2(*reinterpret_cast<__half2*>(&a2.w));
            o1.z += t.x; o1.w += t.y;
            o0.x = (o0.x + acc[0]) * sc; o0.y = (o0.y + acc[1]) * sc;
            o0.z = (o0.z + acc[2]) * sc; o0.w = (o0.w + acc[3]) * sc;
            o1.x = (o1.x + acc[4]) * sc; o1.y = (o1.y + acc[5]) * sc;
            o1.z = (o1.z + acc[6]) * sc; o1.w = (o1.w + acc[7]) * sc;
            float4* out4 = reinterpret_cast<float4*>(out);
            out4[2 * ridx]     = o0;
            out4[2 * ridx + 1] = o1;
        }
    }
}

// ---------------- launch ----------------
extern "C" void kernel_launch(void* const* d_in, const int* in_sizes, int n_in,
                              void* d_out, int out_size) {
    const float* user_emb = (const float*)d_in[0];
    const float* item_emb = (const float*)d_in[1];
    const float* edge_w   = (const float*)d_in[2];
    const int*   edge_row = (const int*)d_in[3];
    const int*   edge_col = (const int*)d_in[4];
    float* out = (float*)d_out;

    k_init_hist<<<2048, 256>>>(user_emb, item_emb, edge_row);
    k_scan1<<<NB, SCAN_CHUNK>>>();
    k_scan23<<<(N_NODES + 255) / 256, 256>>>();
    const int SCAT_BLOCKS = (N_EDGES + 256 * SCAT_PER_THREAD - 1) / (256 * SCAT_PER_THREAD);
    k_scatter<<<SCAT_BLOCKS, 256>>>(edge_row, edge_col, edge_w);

    const int SPMM_BLOCKS = (N_NODES * 32 + 255) / 256;   // one warp per row
    k_spmm<0><<<SPMM_BLOCKS, 256>>>(out);
    k_spmm<1><<<SPMM_BLOCKS, 256>>>(out);
    k_spmm<2><<<SPMM_BLOCKS, 256>>>(out);
}

// round 12
// speedup vs baseline: 1.0633x; 1.0633x over previous
#include <cuda_runtime.h>
#include <cuda_fp16.h>

#define NUM_USERS 100000
#define NUM_ITEMS 100000
#define N_NODES   200000
#define EMB       64
#define N_EDGES   3200000
#define SCAN_CHUNK 1024
#define NB ((N_NODES + SCAN_CHUNK - 1) / SCAN_CHUNK)   // 196

// ---------------- scratch (no allocations allowed) ----------------
// g_cnt is zero at module load and k_scan23 re-zeroes it after use, so every
// call (correctness, capture, every replay) sees zeroed counters.
__device__ int  g_cnt[N_NODES];
__device__ int  g_off[N_NODES];
__device__ int  g_cur[N_NODES];
__device__ int  g_bsum[NB];
__device__ __align__(16) int2   g_edge[N_EDGES];               // {col, w-bits} sorted by row
__device__ __align__(16) __half g_h0[(size_t)N_NODES * EMB];   // ego0
__device__ __align__(16) __half g_h1[(size_t)N_NODES * EMB];   // ego1
__device__ __align__(16) __half g_h2[(size_t)N_NODES * EMB];   // ego2

// -------- init + histogram fused (g_cnt guaranteed zero on entry) ---------
__global__ void k_init_hist(const float* __restrict__ user,
                            const float* __restrict__ item,
                            const int* __restrict__ edge_row) {
    int i = blockIdx.x * blockDim.x + threadIdx.x;
    int stride = gridDim.x * blockDim.x;
    const int NV4 = (N_NODES * EMB) / 4;
    const int UV4 = (NUM_USERS * EMB) / 4;
    const float4* u4 = reinterpret_cast<const float4*>(user);
    const float4* t4 = reinterpret_cast<const float4*>(item);
    uint2* h4 = reinterpret_cast<uint2*>(g_h0);
    for (int j = i; j < NV4; j += stride) {
        float4 f = (j < UV4) ? u4[j] : t4[j - UV4];
        __half2 a = __floats2half2_rn(f.x, f.y);
        __half2 b = __floats2half2_rn(f.z, f.w);
        uint2 p;
        p.x = *reinterpret_cast<unsigned*>(&a);
        p.y = *reinterpret_cast<unsigned*>(&b);
        h4[j] = p;
    }
    for (int e = i; e < N_EDGES; e += stride)
        atomicAdd(&g_cnt[__ldg(&edge_row[e])], 1);
}

// ---------------- scan stage 1: per-chunk inclusive scan ------------------
__global__ void k_scan1() {
    __shared__ int s[SCAN_CHUNK];
    int tid = threadIdx.x;
    int gid = blockIdx.x * SCAN_CHUNK + tid;
    int v = (gid < N_NODES) ? g_cnt[gid] : 0;
    s[tid] = v;
    __syncthreads();
    for (int d = 1; d < SCAN_CHUNK; d <<= 1) {
        int t = (tid >= d) ? s[tid - d] : 0;
        __syncthreads();
        s[tid] += t;
        __syncthreads();
    }
    if (gid < N_NODES) g_off[gid] = s[tid];
    if (tid == SCAN_CHUNK - 1) g_bsum[blockIdx.x] = s[tid];
}

// ---------------- scan stage 2+3 fused + g_cnt reset ----------------------
__global__ void k_scan23() {
    __shared__ int s[256];
    int tid = threadIdx.x;
    s[tid] = (tid < NB) ? g_bsum[tid] : 0;
    __syncthreads();
    for (int d = 1; d < 256; d <<= 1) {
        int t = (tid >= d) ? s[tid - d] : 0;
        __syncthreads();
        s[tid] += t;
        __syncthreads();
    }
    int i = blockIdx.x * blockDim.x + tid;
    if (i < N_NODES) {
        int chunk = i / SCAN_CHUNK;
        int bpre = (chunk == 0) ? 0 : s[chunk - 1];
        int excl = g_off[i] - g_cnt[i] + bpre;
        g_off[i] = excl;
        g_cur[i] = excl;
        g_cnt[i] = 0;              // restore invariant for next replay
    }
}

// ---------------- scatter edges into CSR order (R7 version) --------------
__global__ void k_scatter(const int* __restrict__ edge_row,
                          const int* __restrict__ edge_col,
                          const float* __restrict__ edge_w) {
    int e = blockIdx.x * blockDim.x + threadIdx.x;
    if (e < N_EDGES) {
        int r = __ldg(&edge_row[e]);
        int pos = atomicAdd(&g_cur[r], 1);
        int2 packed;
        packed.x = __ldg(&edge_col[e]);
        packed.y = __float_as_int(__ldg(&edge_w[e]));
        g_edge[pos] = packed;
    }
}

// ---------------- wide-gather CSR SpMM, 8 edges/iteration ----------------
// One warp per row. g = lane>>3 (edge group 0..3), s = lane&7 (16B chunk of
// the 128B fp16 row). Each iteration handles TWO independent 4-edge batches:
// both 128B gathers are in flight simultaneously (width-ILP, no carried
// pipeline state). Next iteration's edge records are prefetched during the
// gathers (same trick as the 274us R7 kernel).
// MODE 0: x=g_h0 -> y=g_h1
// MODE 1: x=g_h1 -> y=g_h2
// MODE 2: x=g_h2;  out = (h1 + h2 + acc)/3
template <int MODE>
__global__ __launch_bounds__(256) void k_spmm(float* __restrict__ out) {
    int warp = (blockIdx.x * blockDim.x + threadIdx.x) >> 5;
    int lane = threadIdx.x & 31;
    if (warp >= N_NODES) return;
    int g = lane >> 3;
    int s = lane & 7;

    int start = g_off[warp];
    int end   = (warp == N_NODES - 1) ? N_EDGES : g_off[warp + 1];

    const __half* xp = (MODE == 0) ? g_h0 : (MODE == 1) ? g_h1 : g_h2;
    const uint4* __restrict__ x4 = reinterpret_cast<const uint4*>(xp);

    float acc[8];
#pragma unroll
    for (int j = 0; j < 8; j++) acc[j] = 0.f;

    if (start < end) {
        // prime: load edge records for the first 8-edge iteration
        int iA = start + g;
        int iB = start + 4 + g;
        bool vA = iA < end, vB = iB < end;
        int2 edA = __ldg(&g_edge[vA ? iA : (end - 1)]);
        int2 edB = __ldg(&g_edge[vB ? iB : (end - 1)]);
        float wA = vA ? __int_as_float(edA.y) : 0.f;
        float wB = vB ? __int_as_float(edB.y) : 0.f;

        for (int e = start; e < end; e += 8) {
            int cA = edA.x, cB = edB.x;
            float wwA = wA, wwB = wB;
            int ne = e + 8;
            if (ne < end) {                         // prefetch next iteration's edges
                int jA = ne + g, jB = ne + 4 + g;
                bool nA = jA < end, nB = jB < end;
                edA = __ldg(&g_edge[nA ? jA : (end - 1)]);
                edB = __ldg(&g_edge[nB ? jB : (end - 1)]);
                wA = nA ? __int_as_float(edA.y) : 0.f;
                wB = nB ? __int_as_float(edB.y) : 0.f;
            }
            // two independent 128B gathers in flight
            uint4 hA = __ldg(&x4[(size_t)cA * 8 + s]);
            uint4 hB = __ldg(&x4[(size_t)cB * 8 + s]);

            float2 f0 = __half22float2(*reinterpret_cast<__half2*>(&hA.x));
            float2 f1 = __half22float2(*reinterpret_cast<__half2*>(&hA.y));
            float2 f2 = __half22float2(*reinterpret_cast<__half2*>(&hA.z));
            float2 f3 = __half22float2(*reinterpret_cast<__half2*>(&hA.w));
            acc[0] = fmaf(wwA, f0.x, acc[0]);
            acc[1] = fmaf(wwA, f0.y, acc[1]);
            acc[2] = fmaf(wwA, f1.x, acc[2]);
            acc[3] = fmaf(wwA, f1.y, acc[3]);
            acc[4] = fmaf(wwA, f2.x, acc[4]);
            acc[5] = fmaf(wwA, f2.y, acc[5]);
            acc[6] = fmaf(wwA, f3.x, acc[6]);
            acc[7] = fmaf(wwA, f3.y, acc[7]);
            f0 = __half22float2(*reinterpret_cast<__half2*>(&hB.x));
            f1 = __half22float2(*reinterpret_cast<__half2*>(&hB.y));
            f2 = __half22float2(*reinterpret_cast<__half2*>(&hB.z));
            f3 = __half22float2(*reinterpret_cast<__half2*>(&hB.w));
            acc[0] = fmaf(wwB, f0.x, acc[0]);
            acc[1] = fmaf(wwB, f0.y, acc[1]);
            acc[2] = fmaf(wwB, f1.x, acc[2]);
            acc[3] = fmaf(wwB, f1.y, acc[3]);
            acc[4] = fmaf(wwB, f2.x, acc[4]);
            acc[5] = fmaf(wwB, f2.y, acc[5]);
            acc[6] = fmaf(wwB, f3.x, acc[6]);
            acc[7] = fmaf(wwB, f3.y, acc[7]);
        }
    }

    // reduce across the 4 edge groups
#pragma unroll
    for (int j = 0; j < 8; j++) {
        acc[j] += __shfl_xor_sync(0xFFFFFFFF, acc[j], 8);
        acc[j] += __shfl_xor_sync(0xFFFFFFFF, acc[j], 16);
    }

    if (g == 0) {
        int ridx = warp * 8 + s;                 // uint4 index of this 16B chunk
        if (MODE != 2) {
            __half2 y0 = __floats2half2_rn(acc[0], acc[1]);
            __half2 y1 = __floats2half2_rn(acc[2], acc[3]);
            __half2 y2 = __floats2half2_rn(acc[4], acc[5]);
            __half2 y3 = __floats2half2_rn(acc[6], acc[7]);
            uint4 pk;
            pk.x = *reinterpret_cast<unsigned*>(&y0);
            pk.y = *reinterpret_cast<unsigned*>(&y1);
            pk.z = *reinterpret_cast<unsigned*>(&y2);
            pk.w = *reinterpret_cast<unsigned*>(&y3);
            uint4* yp = reinterpret_cast<uint4*>((MODE == 0) ? g_h1 : g_h2);
            yp[ridx] = pk;
        } else {
            // out = (ego1 + ego2 + ego3) / 3
            uint4 a1 = __ldg(&reinterpret_cast<const uint4*>(g_h1)[ridx]);
            uint4 a2 = __ldg(&reinterpret_cast<const uint4*>(g_h2)[ridx]);
            const float sc = 1.0f / 3.0f;
            float4 o0, o1;
            float2 t;
            t = __half22float2(*reinterpret_cast<__half2*>(&a1.x));
            o0.x = t.x; o0.y = t.y;
            t = __half22float2(*reinterpret_cast<__half2*>(&a1.y));
            o0.z = t.x; o0.w = t.y;
            t = __half22float2(*reinterpret_cast<__half2*>(&a1.z));
            o1.x = t.x; o1.y = t.y;
            t = __half22float2(*reinterpret_cast<__half2*>(&a1.w));
            o1.z = t.x; o1.w = t.y;
            t = __half22float2(*reinterpret_cast<__half2*>(&a2.x));
            o0.x += t.x; o0.y += t.y;
            t = __half22float2(*reinterpret_cast<__half2*>(&a2.y));
            o0.z += t.x; o0.w += t.y;
            t = __half22float2(*reinterpret_cast<__half2*>(&a2.z));
            o1.x += t.x; o1.y += t.y;
            t = __half22float2(*reinterpret_cast<__half2*>(&a2.w));
            o1.z += t.x; o1.w += t.y;
            o0.x = (o0.x + acc[0]) * sc; o0.y = (o0.y + acc[1]) * sc;
            o0.z = (o0.z + acc[2]) * sc; o0.w = (o0.w + acc[3]) * sc;
            o1.x = (o1.x + acc[4]) * sc; o1.y = (o1.y + acc[5]) * sc;
            o1.z = (o1.z + acc[6]) * sc; o1.w = (o1.w + acc[7]) * sc;
            float4* out4 = reinterpret_cast<float4*>(out);
            out4[2 * ridx]     = o0;
            out4[2 * ridx + 1] = o1;
        }
    }
}

// ---------------- launch ----------------
extern "C" void kernel_launch(void* const* d_in, const int* in_sizes, int n_in,
                              void* d_out, int out_size) {
    const float* user_emb = (const float*)d_in[0];
    const float* item_emb = (const float*)d_in[1];
    const float* edge_w   = (const float*)d_in[2];
    const int*   edge_row = (const int*)d_in[3];
    const int*   edge_col = (const int*)d_in[4];
    float* out = (float*)d_out;

    k_init_hist<<<2048, 256>>>(user_emb, item_emb, edge_row);
    k_scan1<<<NB, SCAN_CHUNK>>>();
    k_scan23<<<(N_NODES + 255) / 256, 256>>>();
    k_scatter<<<(N_EDGES + 255) / 256, 256>>>(edge_row, edge_col, edge_w);

    const int SPMM_BLOCKS = (N_NODES * 32 + 255) / 256;   // one warp per row
    k_spmm<0><<<SPMM_BLOCKS, 256>>>(out);
    k_spmm<1><<<SPMM_BLOCKS, 256>>>(out);
    k_spmm<2><<<SPMM_BLOCKS, 256>>>(out);
}